// round 14
// baseline (speedup 1.0000x reference)
#include <cuda_runtime.h>
#include <cuda_bf16.h>
#include <cstdint>
#include <math.h>

#define NTOK 8192
#define DIM  1024
#define NEXP 8
#define DFF  4096
#define CAP  1280   // int(8192/8 * 1.25)
#define KC1  32     // DIM/32 K-chunks (GEMM1)
#define KC2  128    // DFF/32 K-chunks (GEMM2)
#define NMT  10     // CAP/128 m-tiles

// blocked operand layout constants (bf16 elements)
#define ASTR 40                       // A row stride (32 + 8 pad)
#define BSTR 136                      // B row stride (128 + 8 pad)
#define A_ELE (128 * ASTR)            // 5120 per component
#define B_ELE (32 * BSTR)             // 4352 per component
#define A_BLK (2 * A_ELE)             // hi + lo = 10240 elems = 20480 B
#define B_BLK (2 * B_ELE)             // 8704 elems = 17408 B

// ---------------- scratch (device globals; no allocation allowed) ----------
__device__ __nv_bfloat16 g_A1[(size_t)NEXP * NMT * KC1 * A_BLK];   //  52 MB
__device__ __nv_bfloat16 g_W1b[(size_t)NEXP * 32 * KC1 * B_BLK];   // 143 MB
__device__ __nv_bfloat16 g_W2b[(size_t)NEXP * 8 * KC2 * B_BLK];    // 143 MB
__device__ __nv_bfloat16 g_Hb[(size_t)NEXP * NMT * KC2 * A_BLK];   // 210 MB
__device__ int   g_eidx[NTOK];
__device__ float g_gate[NTOK];
__device__ int   g_kept[NTOK];
__device__ int   g_slot2tok[NEXP * CAP];
__device__ float g_probs_sum[NEXP];
__device__ int   g_count[NEXP];

// ---------------- init ------------------------------------------------------
__global__ void init_kernel() {
    if (threadIdx.x < NEXP) g_probs_sum[threadIdx.x] = 0.f;
}

// ---------------- router: logits, softmax, argmax, gate --------------------
__global__ void router_kernel(const float* __restrict__ x,
                              const float* __restrict__ Wr) {
    __shared__ float s_sum[NEXP];
    if (threadIdx.x < NEXP) s_sum[threadIdx.x] = 0.f;
    __syncthreads();

    int gwarp = (blockIdx.x * blockDim.x + threadIdx.x) >> 5;
    int lane  = threadIdx.x & 31;
    if (gwarp < NTOK) {
        const float* xr = x + (size_t)gwarp * DIM;
        float acc[NEXP];
#pragma unroll
        for (int e = 0; e < NEXP; e++) acc[e] = 0.f;
        for (int d = lane; d < DIM; d += 32) {
            float xv = xr[d];
            const float* wr = Wr + d * NEXP;
#pragma unroll
            for (int e = 0; e < NEXP; e++) acc[e] += xv * wr[e];
        }
#pragma unroll
        for (int e = 0; e < NEXP; e++)
#pragma unroll
            for (int o = 16; o; o >>= 1)
                acc[e] += __shfl_xor_sync(0xffffffffu, acc[e], o);

        if (lane == 0) {
            float mx = acc[0]; int ai = 0;
#pragma unroll
            for (int e = 1; e < NEXP; e++)
                if (acc[e] > mx) { mx = acc[e]; ai = e; }
            float p[NEXP], den = 0.f;
#pragma unroll
            for (int e = 0; e < NEXP; e++) { p[e] = expf(acc[e] - mx); den += p[e]; }
            float inv = 1.f / den;
#pragma unroll
            for (int e = 0; e < NEXP; e++) {
                p[e] *= inv;
                atomicAdd(&s_sum[e], p[e]);
            }
            g_eidx[gwarp] = ai;
            g_gate[gwarp] = p[ai];
        }
    }
    __syncthreads();
    if (threadIdx.x < NEXP) atomicAdd(&g_probs_sum[threadIdx.x], s_sum[threadIdx.x]);
}

// ---------------- scan: order-exact per-expert positions + capacity --------
__global__ void scan_kernel() {
    __shared__ int sbase[NEXP];
    __shared__ int wpre[NEXP][32];
    __shared__ int ctot[NEXP];
    int tid = threadIdx.x, lane = tid & 31, wid = tid >> 5;

    for (int i = tid; i < NEXP * CAP; i += 1024) g_slot2tok[i] = NTOK;
    if (tid < NEXP) sbase[tid] = 0;
    __syncthreads();

    for (int c0 = 0; c0 < NTOK; c0 += 1024) {
        int tok = c0 + tid;
        int e = g_eidx[tok];
        int myrank = 0;
#pragma unroll
        for (int e2 = 0; e2 < NEXP; e2++) {
            unsigned m = __ballot_sync(0xffffffffu, e == e2);
            if (e == e2) myrank = __popc(m & ((1u << lane) - 1u));
            if (lane == 0) wpre[e2][wid] = __popc(m);
        }
        __syncthreads();
        if (wid < NEXP) {
            int v = wpre[wid][lane];
            int incl = v;
#pragma unroll
            for (int o = 1; o < 32; o <<= 1) {
                int t = __shfl_up_sync(0xffffffffu, incl, o);
                if (lane >= o) incl += t;
            }
            wpre[wid][lane] = incl - v;
            if (lane == 31) ctot[wid] = incl;
        }
        __syncthreads();
        int pos  = sbase[e] + wpre[e][wid] + myrank;
        int kept = (pos < CAP) ? 1 : 0;
        g_kept[tok] = kept;
        if (kept) g_slot2tok[e * CAP + pos] = tok;
        else      g_gate[tok] = 0.f;
        __syncthreads();
        if (tid < NEXP) sbase[tid] += ctot[tid];
        __syncthreads();
    }
    if (tid < NEXP) g_count[tid] = sbase[tid] < CAP ? sbase[tid] : CAP;
}

// ---------------- bf16 split helpers ---------------------------------------
__device__ __forceinline__ void bf16_split(float v, __nv_bfloat16& h, __nv_bfloat16& l) {
    h = __float2bfloat16(v);
    l = __float2bfloat16(v - __bfloat162float(h));
}

// ---------------- weight split into blocked layout --------------------------
// W: [E][KD][NB] fp32 -> dst blocks ((e*NT + nt)*KC + kc) of B_BLK bf16
// block interior: hi[k*BSTR + n], lo at +B_ELE.  grid (NT, KC, E), 256 thr.
__global__ void wsplit_kernel(const float* __restrict__ W,
                              __nv_bfloat16* __restrict__ dst,
                              int NT, int KD, int NB) {
    int nt = blockIdx.x, kc = blockIdx.y, e = blockIdx.z;
    int t = threadIdx.x;
    int r  = t >> 3;            // k row 0..31
    int c0 = (t & 7) * 16;      // n col group
    const float* src = W + (size_t)e * KD * NB + (size_t)(kc * 32 + r) * NB
                         + nt * 128 + c0;
    __nv_bfloat16* blk = dst + ((size_t)(e * NT + nt) * gridDim.y + kc) * B_BLK;
    __nv_bfloat16* ph = blk + r * BSTR + c0;
    __nv_bfloat16* pl = ph + B_ELE;
#pragma unroll
    for (int q = 0; q < 4; q++) {
        float4 v = *(const float4*)(src + q * 4);
        __nv_bfloat16 h0, h1, h2, h3, l0, l1, l2, l3;
        bf16_split(v.x, h0, l0); bf16_split(v.y, h1, l1);
        bf16_split(v.z, h2, l2); bf16_split(v.w, h3, l3);
        *(__nv_bfloat162*)(ph + q * 4)     = __nv_bfloat162(h0, h1);
        *(__nv_bfloat162*)(ph + q * 4 + 2) = __nv_bfloat162(h2, h3);
        *(__nv_bfloat162*)(pl + q * 4)     = __nv_bfloat162(l0, l1);
        *(__nv_bfloat162*)(pl + q * 4 + 2) = __nv_bfloat162(l2, l3);
    }
}

// ---------------- gather + split x rows into blocked A ----------------------
// grid (KC1, NMT, E), 256 thr. thread: row = t>>1 (0..127), half = t&1.
__global__ void gatherA_kernel(const float* __restrict__ x) {
    int kc = blockIdx.x, mt = blockIdx.y, e = blockIdx.z;
    int t = threadIdx.x;
    int r = t >> 1, half = t & 1;
    int k0 = half * 16;
    int tok = g_slot2tok[e * CAP + mt * 128 + r];
    __nv_bfloat16* blk = g_A1 + ((size_t)(e * NMT + mt) * KC1 + kc) * A_BLK;
    __nv_bfloat16* ph = blk + r * ASTR + k0;
    __nv_bfloat16* pl = ph + A_ELE;
    if (tok < NTOK) {
        const float* src = x + (size_t)tok * DIM + kc * 32 + k0;
#pragma unroll
        for (int q = 0; q < 4; q++) {
            float4 v = *(const float4*)(src + q * 4);
            __nv_bfloat16 h0, h1, h2, h3, l0, l1, l2, l3;
            bf16_split(v.x, h0, l0); bf16_split(v.y, h1, l1);
            bf16_split(v.z, h2, l2); bf16_split(v.w, h3, l3);
            *(__nv_bfloat162*)(ph + q * 4)     = __nv_bfloat162(h0, h1);
            *(__nv_bfloat162*)(ph + q * 4 + 2) = __nv_bfloat162(h2, h3);
            *(__nv_bfloat162*)(pl + q * 4)     = __nv_bfloat162(l0, l1);
            *(__nv_bfloat162*)(pl + q * 4 + 2) = __nv_bfloat162(l2, l3);
        }
    } else {
        __nv_bfloat162 z(__float2bfloat16(0.f), __float2bfloat16(0.f));
#pragma unroll
        for (int q = 0; q < 8; q++) {
            *(__nv_bfloat162*)(ph + q * 2) = z;
            *(__nv_bfloat162*)(pl + q * 2) = z;
        }
    }
}

// ---------------- fast branch-free tanh via ex2/rcp -------------------------
__device__ __forceinline__ float fast_tanh(float u) {
    float ex;
    asm("ex2.approx.f32 %0, %1;" : "=f"(ex) : "f"(u * 2.885390082f)); // e^{2u}
    float rc;
    asm("rcp.approx.f32 %0, %1;" : "=f"(rc) : "f"(ex + 1.f));
    return 1.f - 2.f * rc;
}
__device__ __forceinline__ float gelu_tanh(float v) {
    const float k0 = 0.7978845608028654f;
    const float k1 = 0.044715f;
    float u = k0 * (v + k1 * v * v * v);
    return 0.5f * v * (1.f + fast_tanh(u));
}

// ============ tensor-core GEMM: bulk-copy feed + 3x bf16 mma.sync ===========
// CTA tile 128x128x32.  256 thr = 8 warps (4m x 2n), warp tile 32x64.
// Loads: per chunk, ONE thread issues 2 cp.async.bulk (A block 20480B,
// B block 17408B) completing on an mbarrier (expect_tx).  Double buffered.
// MODE 0: A = g_A1 blocks, epilogue gelu(v+b1) split into g_Hb blocks
// MODE 1: A = g_Hb blocks, epilogue gate*(v+b2) scattered to out

#define STG_BYTES (A_BLK * 2 + B_BLK * 2)        // 37888
#define OFF_AH 0
#define OFF_AL (A_ELE * 2)                        // 10240 B
#define OFF_BH (A_BLK * 2)                        // 20480 B
#define OFF_BL (A_BLK * 2 + B_ELE * 2)            // 29184 B
#define MB_OFF (2 * STG_BYTES)                    // 75776
#define GEMM_SMEM (MB_OFF + 64)

__device__ __forceinline__ void ldsm_x4(uint32_t* r, uint32_t a) {
    asm volatile("ldmatrix.sync.aligned.m8n8.x4.shared.b16 {%0,%1,%2,%3}, [%4];"
                 : "=r"(r[0]), "=r"(r[1]), "=r"(r[2]), "=r"(r[3]) : "r"(a));
}
__device__ __forceinline__ void ldsm_x4_t(uint32_t* r, uint32_t a) {
    asm volatile("ldmatrix.sync.aligned.m8n8.x4.trans.shared.b16 {%0,%1,%2,%3}, [%4];"
                 : "=r"(r[0]), "=r"(r[1]), "=r"(r[2]), "=r"(r[3]) : "r"(a));
}
__device__ __forceinline__ void mma_bf16(float* d, const uint32_t* a, const uint32_t* b) {
    asm volatile(
        "mma.sync.aligned.m16n8k16.row.col.f32.bf16.bf16.f32 "
        "{%0,%1,%2,%3}, {%4,%5,%6,%7}, {%8,%9}, {%0,%1,%2,%3};"
        : "+f"(d[0]), "+f"(d[1]), "+f"(d[2]), "+f"(d[3])
        : "r"(a[0]), "r"(a[1]), "r"(a[2]), "r"(a[3]), "r"(b[0]), "r"(b[1]));
}

#define MBAR_INIT(addr, cnt) \
    asm volatile("mbarrier.init.shared.b64 [%0], %1;" :: "r"(addr), "r"((uint32_t)(cnt)) : "memory")
#define MBAR_EXPECT_TX(addr, tx) \
    asm volatile("mbarrier.arrive.expect_tx.shared.b64 _, [%0], %1;" :: "r"(addr), "r"((uint32_t)(tx)) : "memory")
#define MBAR_WAIT(addr, ph) do { \
    uint32_t _done = 0; \
    while (!_done) { \
        asm volatile("{\n\t.reg .pred p;\n\t" \
                     "mbarrier.try_wait.parity.shared.b64 p, [%1], %2;\n\t" \
                     "selp.b32 %0, 1, 0, p;\n\t}" \
                     : "=r"(_done) : "r"(addr), "r"((uint32_t)(ph)) : "memory"); \
    } \
} while(0)
__device__ __forceinline__ void bulk_g2s(uint32_t dst, const void* src,
                                         uint32_t bytes, uint32_t mbar) {
    asm volatile("cp.async.bulk.shared::cta.global.mbarrier::complete_tx::bytes "
                 "[%0], [%1], %2, [%3];"
                 :: "r"(dst), "l"(src), "r"(bytes), "r"(mbar) : "memory");
}

template<int MODE>
__global__ __launch_bounds__(256, 2)
void gemm_mma(const float* __restrict__ bias, float* __restrict__ out) {
    extern __shared__ __align__(128) char smem[];
    const int e  = blockIdx.z;
    const int mt = blockIdx.y;
    const int nt = blockIdx.x;
    const int tid = threadIdx.x;
    const int lane = tid & 31;
    const int wid  = tid >> 5;
    const int wm = (wid & 3) * 32;
    const int wn = (wid >> 2) * 64;

    const int NC = (MODE == 0) ? KC1 : KC2;
    const __nv_bfloat16* ablk = (MODE == 0)
        ? g_A1 + (size_t)(e * NMT + mt) * KC1 * A_BLK
        : g_Hb + (size_t)(e * NMT + mt) * KC2 * A_BLK;
    const __nv_bfloat16* bblk = (MODE == 0)
        ? g_W1b + (size_t)(e * 32 + nt) * KC1 * B_BLK
        : g_W2b + (size_t)(e * 8 + nt) * KC2 * B_BLK;

    const uint32_t sb = (uint32_t)__cvta_generic_to_shared(smem);
    const uint32_t mbar0 = sb + MB_OFF;

    if (tid == 0) { MBAR_INIT(mbar0, 1); MBAR_INIT(mbar0 + 8, 1); }
    __syncthreads();
    if (tid == 0) {
#pragma unroll
        for (int s = 0; s < 2; s++) {
            MBAR_EXPECT_TX(mbar0 + s * 8, STG_BYTES);
            bulk_g2s(sb + s * STG_BYTES + OFF_AH, ablk + (size_t)s * A_BLK,
                     A_BLK * 2, mbar0 + s * 8);
            bulk_g2s(sb + s * STG_BYTES + OFF_BH, bblk + (size_t)s * B_BLK,
                     B_BLK * 2, mbar0 + s * 8);
        }
    }

    // ldmatrix lane addressing
    const int lr = lane & 7, lg = lane >> 3;
    const int a_row = wm + (lg & 1) * 8 + lr;
    const int a_col = (lg >> 1) * 8;
    const int b_row = (lg & 1) * 8 + lr;
    const int b_col = wn + (lg >> 1) * 8;

    float acc[2][8][4];
#pragma unroll
    for (int mi = 0; mi < 2; mi++)
#pragma unroll
        for (int nf = 0; nf < 8; nf++)
#pragma unroll
            for (int q = 0; q < 4; q++) acc[mi][nf][q] = 0.f;

    int phase[2] = {0, 0};

    for (int c = 0; c < NC; c++) {
        int b = c & 1;
        MBAR_WAIT(mbar0 + b * 8, phase[b]);
        phase[b] ^= 1;

        uint32_t base = sb + b * STG_BYTES;

#pragma unroll
        for (int ks = 0; ks < 2; ks++) {
            uint32_t ah[2][4], al[2][4];
#pragma unroll
            for (int mi = 0; mi < 2; mi++) {
                uint32_t addr = base +
                    ((a_row + mi * 16) * ASTR + ks * 16 + a_col) * 2;
                ldsm_x4(ah[mi], addr + OFF_AH);
                ldsm_x4(al[mi], addr + OFF_AL);
            }
#pragma unroll
            for (int nf2 = 0; nf2 < 4; nf2++) {
                uint32_t addr = base +
                    ((ks * 16 + b_row) * BSTR + b_col + nf2 * 16) * 2;
                uint32_t rh[4], rl[4];
                ldsm_x4_t(rh, addr + OFF_BH);
                ldsm_x4_t(rl, addr + OFF_BL);
#pragma unroll
                for (int mi = 0; mi < 2; mi++) {
                    mma_bf16(acc[mi][nf2 * 2],     ah[mi], rh);
                    mma_bf16(acc[mi][nf2 * 2 + 1], ah[mi], rh + 2);
                }
#pragma unroll
                for (int mi = 0; mi < 2; mi++) {
                    mma_bf16(acc[mi][nf2 * 2],     ah[mi], rl);
                    mma_bf16(acc[mi][nf2 * 2 + 1], ah[mi], rl + 2);
                }
#pragma unroll
                for (int mi = 0; mi < 2; mi++) {
                    mma_bf16(acc[mi][nf2 * 2],     al[mi], rh);
                    mma_bf16(acc[mi][nf2 * 2 + 1], al[mi], rh + 2);
                }
            }
        }
        __syncthreads();     // all warps done reading buffer b
        if (c + 2 < NC && tid == 0) {
            MBAR_EXPECT_TX(mbar0 + b * 8, STG_BYTES);
            bulk_g2s(base + OFF_AH, ablk + (size_t)(c + 2) * A_BLK,
                     A_BLK * 2, mbar0 + b * 8);
            bulk_g2s(base + OFF_BH, bblk + (size_t)(c + 2) * B_BLK,
                     B_BLK * 2, mbar0 + b * 8);
        }
    }

    // ---- epilogue ----
    const int NB = (MODE == 0) ? DFF : DIM;
    const float* bias_p = bias + e * NB + nt * 128;
#pragma unroll
    for (int mi = 0; mi < 2; mi++) {
#pragma unroll
        for (int rr = 0; rr < 2; rr++) {
            int lrow = wm + mi * 16 + (lane >> 2) + rr * 8;   // row in tile
            if (MODE == 0) {
                __nv_bfloat16* hblk0 = g_Hb + (size_t)(e * NMT + mt) * KC2 * A_BLK;
#pragma unroll
                for (int nf = 0; nf < 8; nf++) {
                    int cl = wn + nf * 8 + (lane & 3) * 2;    // col in tile
                    int cg = nt * 128 + cl;                    // global DFF col
                    int kc = cg >> 5, kin = cg & 31;
                    float v0 = gelu_tanh(acc[mi][nf][rr * 2 + 0] + bias_p[cl]);
                    float v1 = gelu_tanh(acc[mi][nf][rr * 2 + 1] + bias_p[cl + 1]);
                    __nv_bfloat16 h0, h1, l0, l1;
                    bf16_split(v0, h0, l0);
                    bf16_split(v1, h1, l1);
                    __nv_bfloat16* p = hblk0 + (size_t)kc * A_BLK + lrow * ASTR + kin;
                    *(__nv_bfloat162*)p           = __nv_bfloat162(h0, h1);
                    *(__nv_bfloat162*)(p + A_ELE) = __nv_bfloat162(l0, l1);
                }
            } else {
                int tok = g_slot2tok[e * CAP + mt * 128 + lrow];
                if (tok < NTOK) {
                    float gt = g_gate[tok];
                    float* orow = out + (size_t)tok * DIM + nt * 128;
#pragma unroll
                    for (int nf = 0; nf < 8; nf++) {
                        int cl = wn + nf * 8 + (lane & 3) * 2;
                        float2 v;
                        v.x = gt * (acc[mi][nf][rr * 2 + 0] + bias_p[cl]);
                        v.y = gt * (acc[mi][nf][rr * 2 + 1] + bias_p[cl + 1]);
                        *(float2*)(orow + cl) = v;
                    }
                }
            }
        }
    }
}

// ---------------- passthrough for dropped tokens ---------------------------
__global__ void passthrough_kernel(const float* __restrict__ x,
                                   float* __restrict__ out) {
    int tok = blockIdx.x;
    if (g_kept[tok]) return;
    const float4* src = (const float4*)(x + (size_t)tok * DIM);
    float4* dst = (float4*)(out + (size_t)tok * DIM);
    dst[threadIdx.x] = src[threadIdx.x];
}

// ---------------- aux loss --------------------------------------------------
__global__ void aux_kernel(float* __restrict__ out, int out_size) {
    if (out_size <= NTOK * DIM) return;
    float s = 0.f;
    for (int e = 0; e < NEXP; e++) {
        float frac = (float)g_count[e] / (float)NTOK;
        float pm   = g_probs_sum[e] / (float)NTOK;
        s += frac * pm;
    }
    out[NTOK * DIM] = 0.01f * (float)NEXP * s;
}

// ---------------- launch ----------------------------------------------------
extern "C" void kernel_launch(void* const* d_in, const int* in_sizes, int n_in,
                              void* d_out, int out_size) {
    const float* x  = (const float*)d_in[0];
    const float* Wr = (const float*)d_in[1];
    const float* W1 = (const float*)d_in[2];
    const float* b1 = (const float*)d_in[3];
    const float* W2 = (const float*)d_in[4];
    const float* b2 = (const float*)d_in[5];
    float* out = (float*)d_out;

    cudaFuncSetAttribute(gemm_mma<0>,
                         cudaFuncAttributeMaxDynamicSharedMemorySize, GEMM_SMEM);
    cudaFuncSetAttribute(gemm_mma<1>,
                         cudaFuncAttributeMaxDynamicSharedMemorySize, GEMM_SMEM);

    init_kernel<<<1, 32>>>();
    router_kernel<<<NTOK / 8, 256>>>(x, Wr);
    scan_kernel<<<1, 1024>>>();

    // blocked bf16 splits of W1, W2
    {
        __nv_bfloat16 *w1b, *w2b;
        cudaGetSymbolAddress((void**)&w1b, g_W1b);
        cudaGetSymbolAddress((void**)&w2b, g_W2b);
        wsplit_kernel<<<dim3(32, KC1, NEXP), 256>>>(W1, w1b, 32, DIM, DFF);
        wsplit_kernel<<<dim3(8, KC2, NEXP), 256>>>(W2, w2b, 8, DFF, DIM);
    }

    // gather + split x into blocked A (needs scan)
    gatherA_kernel<<<dim3(KC1, NMT, NEXP), 256>>>(x);

    // GEMM1: h = gelu(gather(x) @ W1 + b1)   [M=CAP, N=DFF, K=DIM]
    gemm_mma<0><<<dim3(DFF / 128, NMT, NEXP), 256, GEMM_SMEM>>>(b1, nullptr);

    passthrough_kernel<<<NTOK, 256>>>(x, out);

    // GEMM2: out[tok] = gate * (h @ W2 + b2) [M=CAP, N=DIM, K=DFF]
    gemm_mma<1><<<dim3(DIM / 128, NMT, NEXP), 256, GEMM_SMEM>>>(b2, out);

    aux_kernel<<<1, 1>>>(out, out_size);
}

// round 15
// speedup vs baseline: 1.4269x; 1.4269x over previous
#include <cuda_runtime.h>
#include <cuda_bf16.h>
#include <cstdint>
#include <math.h>

#define NTOK 8192
#define DIM  1024
#define NEXP 8
#define DFF  4096
#define CAP  1280   // int(8192/8 * 1.25)

// ---------------- scratch (device globals; no allocation allowed) ----------
__device__ __nv_bfloat16 g_xh[(size_t)NTOK * DIM];
__device__ __nv_bfloat16 g_xl[(size_t)NTOK * DIM];
__device__ __nv_bfloat16 g_W1h[(size_t)NEXP * DIM * DFF];
__device__ __nv_bfloat16 g_W1l[(size_t)NEXP * DIM * DFF];
__device__ __nv_bfloat16 g_W2h[(size_t)NEXP * DFF * DIM];
__device__ __nv_bfloat16 g_W2l[(size_t)NEXP * DFF * DIM];
__device__ __nv_bfloat16 g_hh[(size_t)NEXP * CAP * DFF];
__device__ __nv_bfloat16 g_hl[(size_t)NEXP * CAP * DFF];
__device__ int   g_eidx[NTOK];
__device__ float g_gate[NTOK];
__device__ int   g_kept[NTOK];
__device__ int   g_slot2tok[NEXP * CAP];
__device__ float g_probs_sum[NEXP];
__device__ int   g_count[NEXP];

// ---------------- init ------------------------------------------------------
__global__ void init_kernel() {
    if (threadIdx.x < NEXP) g_probs_sum[threadIdx.x] = 0.f;
}

// ---------------- router: logits, softmax, argmax, gate --------------------
__global__ void router_kernel(const float* __restrict__ x,
                              const float* __restrict__ Wr) {
    __shared__ float s_sum[NEXP];
    if (threadIdx.x < NEXP) s_sum[threadIdx.x] = 0.f;
    __syncthreads();

    int gwarp = (blockIdx.x * blockDim.x + threadIdx.x) >> 5;
    int lane  = threadIdx.x & 31;
    if (gwarp < NTOK) {
        const float* xr = x + (size_t)gwarp * DIM;
        float acc[NEXP];
#pragma unroll
        for (int e = 0; e < NEXP; e++) acc[e] = 0.f;
        for (int d = lane; d < DIM; d += 32) {
            float xv = xr[d];
            const float* wr = Wr + d * NEXP;
#pragma unroll
            for (int e = 0; e < NEXP; e++) acc[e] += xv * wr[e];
        }
#pragma unroll
        for (int e = 0; e < NEXP; e++)
#pragma unroll
            for (int o = 16; o; o >>= 1)
                acc[e] += __shfl_xor_sync(0xffffffffu, acc[e], o);

        if (lane == 0) {
            float mx = acc[0]; int ai = 0;
#pragma unroll
            for (int e = 1; e < NEXP; e++)
                if (acc[e] > mx) { mx = acc[e]; ai = e; }
            float p[NEXP], den = 0.f;
#pragma unroll
            for (int e = 0; e < NEXP; e++) { p[e] = expf(acc[e] - mx); den += p[e]; }
            float inv = 1.f / den;
#pragma unroll
            for (int e = 0; e < NEXP; e++) {
                p[e] *= inv;
                atomicAdd(&s_sum[e], p[e]);
            }
            g_eidx[gwarp] = ai;
            g_gate[gwarp] = p[ai];
        }
    }
    __syncthreads();
    if (threadIdx.x < NEXP) atomicAdd(&g_probs_sum[threadIdx.x], s_sum[threadIdx.x]);
}

// ---------------- scan: order-exact per-expert positions + capacity --------
__global__ void scan_kernel() {
    __shared__ int sbase[NEXP];
    __shared__ int wpre[NEXP][32];
    __shared__ int ctot[NEXP];
    int tid = threadIdx.x, lane = tid & 31, wid = tid >> 5;

    for (int i = tid; i < NEXP * CAP; i += 1024) g_slot2tok[i] = NTOK;
    if (tid < NEXP) sbase[tid] = 0;
    __syncthreads();

    for (int c0 = 0; c0 < NTOK; c0 += 1024) {
        int tok = c0 + tid;
        int e = g_eidx[tok];
        int myrank = 0;
#pragma unroll
        for (int e2 = 0; e2 < NEXP; e2++) {
            unsigned m = __ballot_sync(0xffffffffu, e == e2);
            if (e == e2) myrank = __popc(m & ((1u << lane) - 1u));
            if (lane == 0) wpre[e2][wid] = __popc(m);
        }
        __syncthreads();
        if (wid < NEXP) {
            int v = wpre[wid][lane];
            int incl = v;
#pragma unroll
            for (int o = 1; o < 32; o <<= 1) {
                int t = __shfl_up_sync(0xffffffffu, incl, o);
                if (lane >= o) incl += t;
            }
            wpre[wid][lane] = incl - v;
            if (lane == 31) ctot[wid] = incl;
        }
        __syncthreads();
        int pos  = sbase[e] + wpre[e][wid] + myrank;
        int kept = (pos < CAP) ? 1 : 0;
        g_kept[tok] = kept;
        if (kept) g_slot2tok[e * CAP + pos] = tok;
        else      g_gate[tok] = 0.f;
        __syncthreads();
        if (tid < NEXP) sbase[tid] += ctot[tid];
        __syncthreads();
    }
    if (tid < NEXP) g_count[tid] = sbase[tid] < CAP ? sbase[tid] : CAP;
}

// ---------------- bf16 split: v = hi + lo (both rn) ------------------------
__device__ __forceinline__ void bf16_split(float v, __nv_bfloat16& h, __nv_bfloat16& l) {
    h = __float2bfloat16(v);
    l = __float2bfloat16(v - __bfloat162float(h));
}

// elementwise split kernel: 4 elems/thread (coalesced)
__global__ void split_kernel(const float* __restrict__ src,
                             __nv_bfloat16* __restrict__ dh,
                             __nv_bfloat16* __restrict__ dl, size_t n4) {
    size_t i = (size_t)blockIdx.x * blockDim.x + threadIdx.x;
    if (i >= n4) return;
    float4 v = ((const float4*)src)[i];
    __nv_bfloat16 h0, h1, h2, h3, l0, l1, l2, l3;
    bf16_split(v.x, h0, l0);
    bf16_split(v.y, h1, l1);
    bf16_split(v.z, h2, l2);
    bf16_split(v.w, h3, l3);
    ((__nv_bfloat162*)dh)[i * 2]     = __nv_bfloat162(h0, h1);
    ((__nv_bfloat162*)dh)[i * 2 + 1] = __nv_bfloat162(h2, h3);
    ((__nv_bfloat162*)dl)[i * 2]     = __nv_bfloat162(l0, l1);
    ((__nv_bfloat162*)dl)[i * 2 + 1] = __nv_bfloat162(l2, l3);
}

// ---------------- fast branch-free tanh + GELU ------------------------------
__device__ __forceinline__ float fast_tanh(float u) {
    float ex;
    asm("ex2.approx.f32 %0, %1;" : "=f"(ex) : "f"(u * 2.885390082f)); // e^{2u}
    float rc;
    asm("rcp.approx.f32 %0, %1;" : "=f"(rc) : "f"(ex + 1.f));
    return 1.f - 2.f * rc;
}
__device__ __forceinline__ float gelu_tanh(float v) {
    const float k0 = 0.7978845608028654f;
    const float k1 = 0.044715f;
    float u = k0 * (v + k1 * v * v * v);
    return 0.5f * v * (1.f + fast_tanh(u));
}

// ============ tensor-core GEMM via 3x bf16 mma.sync (split operands) ========
// CTA tile 128(M) x 128(N) x 32(K). 256 threads = 8 warps (4m x 2n),
// warp tile 32x64 = 2 m-frags x 8 n-frags of m16n8k16.
// a*b ~= a0*b0 + a0*b1 + a1*b0 with a0,b0 bf16(rn) and a1,b1 residuals.
// 2-stage cp.async double-buffer; 2 CTAs/SM for cross-CTA latency hiding.
// MODE 0: A = gathered split-x rows -> epilogue gelu(v+b1) split into g_hh/g_hl
// MODE 1: A = split-h rows          -> epilogue gate*(v+b2) scattered to out

#define ASTR 40     // bf16 per A row (32 + 8 pad)
#define BSTR 136    // bf16 per B row (128 + 8 pad)
#define OFF_AH 0
#define OFF_AL (128 * ASTR)                  // 5120
#define OFF_BH (2 * 128 * ASTR)              // 10240
#define OFF_BL (2 * 128 * ASTR + 32 * BSTR)  // 14592
#define STAGE_ELEMS (2 * 128 * ASTR + 2 * 32 * BSTR)   // 18944 bf16 = 37888 B
#define NSTAGE 2
#define GEMM_SMEM (STAGE_ELEMS * NSTAGE * 2)           // 75776 B

__device__ __forceinline__ void cpa16(uint32_t dst, const void* src, int src_size) {
    asm volatile("cp.async.cg.shared.global [%0], [%1], 16, %2;"
                 :: "r"(dst), "l"(src), "r"(src_size));
}
__device__ __forceinline__ void cpa_commit() {
    asm volatile("cp.async.commit_group;" ::: "memory");
}
template<int N> __device__ __forceinline__ void cpa_wait() {
    asm volatile("cp.async.wait_group %0;" :: "n"(N) : "memory");
}

__device__ __forceinline__ void ldsm_x4(uint32_t* r, uint32_t a) {
    asm volatile("ldmatrix.sync.aligned.m8n8.x4.shared.b16 {%0,%1,%2,%3}, [%4];"
                 : "=r"(r[0]), "=r"(r[1]), "=r"(r[2]), "=r"(r[3]) : "r"(a));
}
__device__ __forceinline__ void ldsm_x4_t(uint32_t* r, uint32_t a) {
    asm volatile("ldmatrix.sync.aligned.m8n8.x4.trans.shared.b16 {%0,%1,%2,%3}, [%4];"
                 : "=r"(r[0]), "=r"(r[1]), "=r"(r[2]), "=r"(r[3]) : "r"(a));
}

__device__ __forceinline__ void mma_bf16(float* d, const uint32_t* a, const uint32_t* b) {
    asm volatile(
        "mma.sync.aligned.m16n8k16.row.col.f32.bf16.bf16.f32 "
        "{%0,%1,%2,%3}, {%4,%5,%6,%7}, {%8,%9}, {%0,%1,%2,%3};"
        : "+f"(d[0]), "+f"(d[1]), "+f"(d[2]), "+f"(d[3])
        : "r"(a[0]), "r"(a[1]), "r"(a[2]), "r"(a[3]), "r"(b[0]), "r"(b[1]));
}

template<int KDIM, int NB, int MODE>
__global__ __launch_bounds__(256, 2)
void gemm_mma(const float* __restrict__ bias, float* __restrict__ out) {
    extern __shared__ __align__(16) __nv_bfloat16 smem[];
    const int e  = blockIdx.z;
    const int mt = blockIdx.y;
    const int nt = blockIdx.x;
    const int tid = threadIdx.x;
    const int lane = tid & 31;
    const int wid  = tid >> 5;
    const int wm = (wid & 3) * 32;        // warp m offset
    const int wn = (wid >> 2) * 64;       // warp n offset

    // ---- per-thread global source pointers (A: 2 thr/row, B: 8 thr/row) ----
    const int arow = tid >> 1;
    const int ahalf = tid & 1;            // 16-bf16 half of the 32-chunk
    const __nv_bfloat16 *aph, *apl;
    int asz = 16;
    if (MODE == 0) {
        int tok = g_slot2tok[e * CAP + mt * 128 + arow];
        if (tok >= NTOK) { tok = 0; asz = 0; }       // zero-fill dropped slot
        aph = g_xh + (size_t)tok * DIM + ahalf * 16;
        apl = g_xl + (size_t)tok * DIM + ahalf * 16;
    } else {
        size_t off = (size_t)(e * CAP + mt * 128 + arow) * KDIM + ahalf * 16;
        aph = g_hh + off;
        apl = g_hl + off;
    }
    const size_t boff = (size_t)e * KDIM * NB + (size_t)(tid >> 3) * NB
                      + nt * 128 + (tid & 7) * 16;
    const __nv_bfloat16* bph = ((MODE == 0) ? g_W1h : g_W2h) + boff;
    const __nv_bfloat16* bpl = ((MODE == 0) ? g_W1l : g_W2l) + boff;

    const uint32_t smem_b = (uint32_t)__cvta_generic_to_shared(smem);
    const uint32_t sa = (arow * ASTR + ahalf * 16) * 2;           // bytes
    const uint32_t sb = ((tid >> 3) * BSTR + (tid & 7) * 16) * 2; // bytes

    const int NC = KDIM / 32;

    auto load_stage = [&](int s, int k0) {
        uint32_t base = smem_b + s * STAGE_ELEMS * 2;
        cpa16(base + OFF_AH * 2 + sa,      aph + k0, asz);
        cpa16(base + OFF_AH * 2 + sa + 16, aph + k0 + 8, asz);
        cpa16(base + OFF_AL * 2 + sa,      apl + k0, asz);
        cpa16(base + OFF_AL * 2 + sa + 16, apl + k0 + 8, asz);
        const __nv_bfloat16* bh = bph + (size_t)k0 * NB;
        const __nv_bfloat16* bl = bpl + (size_t)k0 * NB;
        cpa16(base + OFF_BH * 2 + sb,      bh, 16);
        cpa16(base + OFF_BH * 2 + sb + 16, bh + 8, 16);
        cpa16(base + OFF_BL * 2 + sb,      bl, 16);
        cpa16(base + OFF_BL * 2 + sb + 16, bl + 8, 16);
        cpa_commit();
    };

    load_stage(0, 0);
    load_stage(1, 32);

    // ---- ldmatrix lane addressing (stage-invariant parts) ----
    const int lr = lane & 7, lg = lane >> 3;
    // A: row = wm + mi*16 + (lg&1)*8 + lr ; col = ks*16 + (lg>>1)*8
    const int a_row = wm + (lg & 1) * 8 + lr;
    const int a_col = (lg >> 1) * 8;
    // B(trans): row(k) = ks*16 + (lg&1)*8 + lr ; col(n) = wn + nf2*16 + (lg>>1)*8
    const int b_row = (lg & 1) * 8 + lr;
    const int b_col = wn + (lg >> 1) * 8;

    float acc[2][8][4];
#pragma unroll
    for (int mi = 0; mi < 2; mi++)
#pragma unroll
        for (int nf = 0; nf < 8; nf++)
#pragma unroll
            for (int q = 0; q < 4; q++) acc[mi][nf][q] = 0.f;

    for (int c = 0; c < NC; c++) {
        cpa_wait<1>();
        __syncthreads();

        uint32_t base = smem_b + (c & 1) * STAGE_ELEMS * 2;

#pragma unroll
        for (int ks = 0; ks < 2; ks++) {
            uint32_t ah[2][4], al[2][4];
#pragma unroll
            for (int mi = 0; mi < 2; mi++) {
                uint32_t addr = base +
                    ((a_row + mi * 16) * ASTR + ks * 16 + a_col) * 2;
                ldsm_x4(ah[mi], addr + OFF_AH * 2);
                ldsm_x4(al[mi], addr + OFF_AL * 2);
            }
            // B processed one hi/lo ldmatrix group (2 nf) at a time: low regs
#pragma unroll
            for (int nf2 = 0; nf2 < 4; nf2++) {
                uint32_t addr = base +
                    ((ks * 16 + b_row) * BSTR + b_col + nf2 * 16) * 2;
                uint32_t rh[4], rl[4];
                ldsm_x4_t(rh, addr + OFF_BH * 2);
                ldsm_x4_t(rl, addr + OFF_BL * 2);
#pragma unroll
                for (int mi = 0; mi < 2; mi++) {
                    mma_bf16(acc[mi][nf2 * 2],     ah[mi], rh);
                    mma_bf16(acc[mi][nf2 * 2 + 1], ah[mi], rh + 2);
                }
#pragma unroll
                for (int mi = 0; mi < 2; mi++) {
                    mma_bf16(acc[mi][nf2 * 2],     ah[mi], rl);
                    mma_bf16(acc[mi][nf2 * 2 + 1], ah[mi], rl + 2);
                }
#pragma unroll
                for (int mi = 0; mi < 2; mi++) {
                    mma_bf16(acc[mi][nf2 * 2],     al[mi], rh);
                    mma_bf16(acc[mi][nf2 * 2 + 1], al[mi], rh + 2);
                }
            }
        }
        __syncthreads();
        // refill the buffer just consumed with chunk c+2
        if (c + 2 < NC) load_stage(c & 1, (c + 2) * 32);
        else            cpa_commit();
    }

    // ---- epilogue ----
    const float* bias_p = bias + e * NB + nt * 128;
#pragma unroll
    for (int mi = 0; mi < 2; mi++) {
#pragma unroll
        for (int rr = 0; rr < 2; rr++) {
            int lrow = wm + mi * 16 + (lane >> 2) + rr * 8;   // row in tile
            int slot = e * CAP + mt * 128 + lrow;
            if (MODE == 0) {
                size_t rowoff = (size_t)slot * DFF + nt * 128;
#pragma unroll
                for (int nf = 0; nf < 8; nf++) {
                    int cn = wn + nf * 8 + (lane & 3) * 2;
                    float v0 = gelu_tanh(acc[mi][nf][rr * 2 + 0] + bias_p[cn]);
                    float v1 = gelu_tanh(acc[mi][nf][rr * 2 + 1] + bias_p[cn + 1]);
                    __nv_bfloat16 h0, h1, l0, l1;
                    bf16_split(v0, h0, l0);
                    bf16_split(v1, h1, l1);
                    *(__nv_bfloat162*)(g_hh + rowoff + cn) = __nv_bfloat162(h0, h1);
                    *(__nv_bfloat162*)(g_hl + rowoff + cn) = __nv_bfloat162(l0, l1);
                }
            } else {
                int tok = g_slot2tok[slot];
                if (tok < NTOK) {
                    float gt = g_gate[tok];
                    float* orow = out + (size_t)tok * DIM + nt * 128;
#pragma unroll
                    for (int nf = 0; nf < 8; nf++) {
                        int cn = wn + nf * 8 + (lane & 3) * 2;
                        float2 v;
                        v.x = gt * (acc[mi][nf][rr * 2 + 0] + bias_p[cn]);
                        v.y = gt * (acc[mi][nf][rr * 2 + 1] + bias_p[cn + 1]);
                        *(float2*)(orow + cn) = v;
                    }
                }
            }
        }
    }
}

// ---------------- passthrough for dropped tokens ---------------------------
__global__ void passthrough_kernel(const float* __restrict__ x,
                                   float* __restrict__ out) {
    int tok = blockIdx.x;
    if (g_kept[tok]) return;
    const float4* src = (const float4*)(x + (size_t)tok * DIM);
    float4* dst = (float4*)(out + (size_t)tok * DIM);
    dst[threadIdx.x] = src[threadIdx.x];
}

// ---------------- aux loss --------------------------------------------------
__global__ void aux_kernel(float* __restrict__ out, int out_size) {
    if (out_size <= NTOK * DIM) return;
    float s = 0.f;
    for (int e = 0; e < NEXP; e++) {
        float frac = (float)g_count[e] / (float)NTOK;
        float pm   = g_probs_sum[e] / (float)NTOK;
        s += frac * pm;
    }
    out[NTOK * DIM] = 0.01f * (float)NEXP * s;
}

// ---------------- launch ----------------------------------------------------
extern "C" void kernel_launch(void* const* d_in, const int* in_sizes, int n_in,
                              void* d_out, int out_size) {
    const float* x  = (const float*)d_in[0];
    const float* Wr = (const float*)d_in[1];
    const float* W1 = (const float*)d_in[2];
    const float* b1 = (const float*)d_in[3];
    const float* W2 = (const float*)d_in[4];
    const float* b2 = (const float*)d_in[5];
    float* out = (float*)d_out;

    cudaFuncSetAttribute(gemm_mma<DIM, DFF, 0>,
                         cudaFuncAttributeMaxDynamicSharedMemorySize, GEMM_SMEM);
    cudaFuncSetAttribute(gemm_mma<DFF, DIM, 1>,
                         cudaFuncAttributeMaxDynamicSharedMemorySize, GEMM_SMEM);

    init_kernel<<<1, 32>>>();
    router_kernel<<<NTOK / 8, 256>>>(x, Wr);
    scan_kernel<<<1, 1024>>>();

    // bf16 splits of x, W1, W2
    {
        __nv_bfloat16 *xh, *xl, *w1h, *w1l, *w2h, *w2l;
        cudaGetSymbolAddress((void**)&xh,  g_xh);
        cudaGetSymbolAddress((void**)&xl,  g_xl);
        cudaGetSymbolAddress((void**)&w1h, g_W1h);
        cudaGetSymbolAddress((void**)&w1l, g_W1l);
        cudaGetSymbolAddress((void**)&w2h, g_W2h);
        cudaGetSymbolAddress((void**)&w2l, g_W2l);
        size_t nx = (size_t)NTOK * DIM / 4;
        size_t nw = (size_t)NEXP * DIM * DFF / 4;
        split_kernel<<<(unsigned)((nx + 255) / 256), 256>>>(x,  xh,  xl,  nx);
        split_kernel<<<(unsigned)((nw + 255) / 256), 256>>>(W1, w1h, w1l, nw);
        split_kernel<<<(unsigned)((nw + 255) / 256), 256>>>(W2, w2h, w2l, nw);
    }

    // GEMM1: h = gelu(gather(x) @ W1 + b1)   [M=CAP, N=DFF, K=DIM]
    gemm_mma<DIM, DFF, 0><<<dim3(DFF / 128, CAP / 128, NEXP), 256, GEMM_SMEM>>>(b1, nullptr);

    passthrough_kernel<<<NTOK, 256>>>(x, out);

    // GEMM2: out[tok] = gate * (h @ W2 + b2) [M=CAP, N=DIM, K=DFF]
    gemm_mma<DFF, DIM, 1><<<dim3(DIM / 128, CAP / 128, NEXP), 256, GEMM_SMEM>>>(b2, out);

    aux_kernel<<<1, 1>>>(out, out_size);
}